// round 2
// baseline (speedup 1.0000x reference)
#include <cuda_runtime.h>
#include <math.h>

// Problem constants
#define NB    64
#define NH    512
#define NW    512
#define NPTS  200

#define EPS_LO 0.498f
#define EPS_HI 0.502f
#define BLCAP  8192

// ---------------- scratch (device globals, no allocation) ----------------
__device__ unsigned g_minb[NB];
__device__ unsigned g_maxb[NB];
// g_cnt[half][batch][row]: half 0 = cols [0,256) (contour 1),
//                          half 1 = cols [256,512) (contour 2, reversed image)
__device__ float    g_cnt[2][NB][NH];
__device__ unsigned g_bl_n[NB];
__device__ unsigned g_bl_key[NB][BLCAP];   // (half<<9) | row
__device__ float    g_bl_val[NB][BLCAP];

// ---------------- K0: reset scratch ----------------
__global__ void k0_init() {
    int i = threadIdx.x;
    if (i < NB) {
        g_minb[i] = 0x7f800000u;  // +inf bits
        g_maxb[i] = 0u;           // 0.0f bits (input is uniform(0,1), nonneg)
        g_bl_n[i] = 0u;
    }
}

// ---------------- KA: fused single pass ----------------
// One warp per row: per-row base counts (v > EPS_LO) for both halves,
// per-batch min/max, and borderline-value capture for later correction.
// grid 4096, block 256 (8 warps).
__global__ void kA_pass(const float4* __restrict__ in) {
    int gwarp = (blockIdx.x * blockDim.x + threadIdx.x) >> 5;  // 0..32767
    int lane  = threadIdx.x & 31;
    int b   = gwarp >> 9;
    int row = gwarp & 511;

    const float4* p = in + ((size_t)(b * NH + row)) * 256;  // 256 float4 per row
    unsigned cL = 0, cR = 0;
    float mn = 1e30f, mx = -1e30f;
#pragma unroll
    for (int i = 0; i < 8; i++) {
        float4 v = p[lane + i * 32];
        float a = v.y, c = v.w;                 // channel-1 of two pixels
        mn = fminf(mn, fminf(a, c));
        mx = fmaxf(mx, fmaxf(a, c));
        unsigned cnt = (unsigned)(a > EPS_LO) + (unsigned)(c > EPS_LO);
        if (i < 4) cL += cnt; else cR += cnt;   // float4 idx <128 -> cols <256
        unsigned half = (i < 4) ? 0u : 1u;
        if (a > EPS_LO && a <= EPS_HI) {        // borderline (rare)
            unsigned idx = atomicAdd(&g_bl_n[b], 1u);
            if (idx < BLCAP) { g_bl_key[b][idx] = (half << 9) | row; g_bl_val[b][idx] = a; }
        }
        if (c > EPS_LO && c <= EPS_HI) {
            unsigned idx = atomicAdd(&g_bl_n[b], 1u);
            if (idx < BLCAP) { g_bl_key[b][idx] = (half << 9) | row; g_bl_val[b][idx] = c; }
        }
    }
    cL = __reduce_add_sync(0xffffffffu, cL);
    cR = __reduce_add_sync(0xffffffffu, cR);
    if (lane == 0) {
        g_cnt[0][b][row] = (float)cL;
        g_cnt[1][b][row] = (float)cR;
    }

    // block-level min/max -> one atomic pair per block
#pragma unroll
    for (int o = 16; o; o >>= 1) {
        mn = fminf(mn, __shfl_xor_sync(0xffffffffu, mn, o));
        mx = fmaxf(mx, __shfl_xor_sync(0xffffffffu, mx, o));
    }
    __shared__ float smn[8], smx[8];
    int w = threadIdx.x >> 5;
    if (lane == 0) { smn[w] = mn; smx[w] = mx; }
    __syncthreads();
    if (threadIdx.x == 0) {
#pragma unroll
        for (int i = 1; i < 8; i++) { mn = fminf(mn, smn[i]); mx = fmaxf(mx, smx[i]); }
        atomicMin(&g_minb[b], __float_as_uint(mn));
        atomicMax(&g_maxb[b], __float_as_uint(mx));
    }
}

// ---------------- KB: borderline correction ----------------
// One block per batch. Re-test each borderline value with the exact
// predicate (v - mn) > 0.5*(mx - mn); decrement base count on failure.
// Fallback full recount if the threshold lands outside the capture window
// or the capture buffer overflowed (never expected for this data).
__global__ void kB_fix(const float4* __restrict__ in) {
    int b = blockIdx.x;
    float mn = __uint_as_float(g_minb[b]);
    float mx = __uint_as_float(g_maxb[b]);
    float h  = 0.5f * (mx - mn);
    unsigned n = g_bl_n[b];

    // Safety: predicate must be false for all v <= EPS_LO and true for all
    // v > EPS_HI. Predicate is monotone in v, so check the window edges.
    bool ok = !((EPS_LO - mn) > h) && ((EPS_HI - mn) >= h) && (n <= BLCAP);

    if (ok) {
        for (unsigned i = threadIdx.x; i < n; i += blockDim.x) {
            unsigned key = g_bl_key[b][i];
            float v = g_bl_val[b][i];
            if (!((v - mn) > h)) {
                atomicAdd(&g_cnt[key >> 9][b][key & 511], -1.0f);
            }
        }
    } else {
        // never-taken exact fallback: full recount of this batch
        int wid = threadIdx.x >> 5, lane = threadIdx.x & 31;
        for (int row = wid; row < NH; row += 8) {
            const float4* p = in + ((size_t)(b * NH + row)) * 256;
            unsigned cL = 0, cR = 0;
#pragma unroll
            for (int i = 0; i < 8; i++) {
                float4 v = p[lane + i * 32];
                unsigned c = (unsigned)((v.y - mn) > h) + (unsigned)((v.w - mn) > h);
                if (i < 4) cL += c; else cR += c;
            }
            cL = __reduce_add_sync(0xffffffffu, cL);
            cR = __reduce_add_sync(0xffffffffu, cR);
            if (lane == 0) { g_cnt[0][b][row] = (float)cL; g_cnt[1][b][row] = (float)cR; }
        }
    }
}

// ---------------- K3: per (batch, contour) resampling ----------------
// grid 128 (= batch*2), block 512.
__global__ void k3_contour(float* __restrict__ out) {
    const float PI_F   = 3.14159265358979f;
    const float TWO_PI = 6.283185307179586f;
    const float TT0    = (float)(M_PI / 2.0);
    const float DT     = (float)(M_PI / 200.0);

    int unit = blockIdx.x;
    int b = unit >> 1, c = unit & 1;
    int tid = threadIdx.x;  // == row for phase 1

    __shared__ float2 s_rt[NH];    // (tt, r) packed
    __shared__ float s_red[16];
    __shared__ float s_bounds[2];

    float x1 = g_cnt[c][b][tid];
    float xa = fminf(x1, 1.0f);

    // block reduce xa: warps 0..7 cover rows 0..255 (top), 8..15 bottom
    float s = xa;
#pragma unroll
    for (int o = 16; o; o >>= 1) s += __shfl_xor_sync(0xffffffffu, s, o);
    if ((tid & 31) == 0) s_red[tid >> 5] = s;
    __syncthreads();
    if (tid == 0) {
        float st = 0.f, sb = 0.f;
#pragma unroll
        for (int i = 0; i < 8; i++)  st += s_red[i];
#pragma unroll
        for (int i = 8; i < 16; i++) sb += s_red[i];
        s_bounds[0] = 256.0f - st;   // ythtop
        s_bounds[1] = 256.0f + sb;   // ythbottom
    }
    __syncthreads();
    float top = s_bounds[0], bot = s_bounds[1];

    float y1 = fminf(fmaxf((float)tid, top), bot);
    float yc = y1 - 256.0f;
    float xc = -x1;
    float r  = sqrtf(xc * xc + yc * yc);
    float tt = atan2f(yc, xc);
    if (tt < 0.0f) tt += TWO_PI;     // fix_radians: map to [0, 2pi)
    s_rt[tid] = make_float2(tt, r);
    __syncthreads();

    // 2 threads per output point; each covers 256 source rows.
    // Only the nearest period offset can have d^2 < 1 (offsets are 2*pi
    // apart), the other two clamp to exp(-100) ~ 0 and are dropped.
    int n = tid >> 1;               // 0..255 (only 0..199 real)
    int hh = tid & 1;
    float ttn = TT0 + (float)n * DT;
    float num = 0.f, den = 0.f;
    int base = hh << 8;
#pragma unroll 8
    for (int m = 0; m < 256; m++) {
        float2 tr = s_rt[base + m];
        float d = tr.x - ttn;                    // in (-3pi/2, 3pi/2)
        d = (d >  PI_F) ? d - TWO_PI : d;        // wrap to [-pi, pi]
        d = (d < -PI_F) ? d + TWO_PI : d;
        float d2 = fminf(d * d, 1.0f);
        float w  = __expf(-100.0f * d2);
        den += w;
        num = fmaf(w, tr.y, num);
    }
    num += __shfl_xor_sync(0xffffffffu, num, 1);
    den += __shfl_xor_sync(0xffffffffu, den, 1);

    if (hh == 0 && n < NPTS) {
        float rn = num / den;
        float x = fmaf(rn, cosf(ttn), 256.0f);
        float y = fmaf(rn, sinf(ttn), 256.0f);
        int idx; float xo;
        if (c == 0) { idx = n;        xo = x; }
        else        { idx = 399 - n;  xo = 512.0f - x; }
        out[((size_t)b * 400 + idx) * 2 + 0] = xo;
        out[((size_t)b * 400 + idx) * 2 + 1] = y;
    }
}

extern "C" void kernel_launch(void* const* d_in, const int* in_sizes, int n_in,
                              void* d_out, int out_size) {
    const float4* in = (const float4*)d_in[0];
    float* out = (float*)d_out;

    k0_init<<<1, 64>>>();
    kA_pass<<<4096, 256>>>(in);
    kB_fix<<<64, 256>>>(in);
    k3_contour<<<128, 512>>>(out);
}

// round 3
// speedup vs baseline: 1.6078x; 1.6078x over previous
#include <cuda_runtime.h>
#include <math.h>

// Problem constants
#define NB    64
#define NH    512
#define NW    512
#define NPTS  200

#define EPS_LO 0.4999f
#define EPS_HI 0.5001f
#define BLCAP  4096

// ---------------- scratch (device globals, no allocation) ----------------
__device__ unsigned g_minb[NB];
__device__ unsigned g_maxb[NB];
// g_cnt[half][batch][row]: half 0 = cols [0,256), half 1 = cols [256,512)
__device__ float    g_cnt[2][NB][NH];
__device__ unsigned g_bl_n[NB];
__device__ unsigned g_bl_key[NB][BLCAP];   // (half<<9) | row
__device__ float    g_bl_val[NB][BLCAP];

// ---------------- K0: reset scratch ----------------
__global__ void k0_init() {
    int i = threadIdx.x;
    if (i < NB) {
        g_minb[i] = 0x7f800000u;  // +inf bits
        g_maxb[i] = 0u;           // 0.0f bits (input is uniform(0,1), nonneg)
        g_bl_n[i] = 0u;
    }
}

// ---------------- KA: fused single pass (DRAM-bound) ----------------
// One warp per row. Loads are front-batched (MLP=8) BEFORE any branching.
// Per-row base counts use fixed threshold EPS_LO; values in the tiny
// (EPS_LO, EPS_HI] window (~52/batch) are captured for exact correction.
__global__ void kA_pass(const float4* __restrict__ in) {
    int gwarp = (blockIdx.x * blockDim.x + threadIdx.x) >> 5;  // 0..32767
    int lane  = threadIdx.x & 31;
    int b   = gwarp >> 9;
    int row = gwarp & 511;

    const float4* p = in + ((size_t)(b * NH + row)) * 256;  // 256 float4/row

    // front-batched loads: 8 independent LDG.128 in flight
    float a[16];
#pragma unroll
    for (int i = 0; i < 8; i++) {
        float4 t = p[lane + i * 32];
        a[2 * i]     = t.y;           // channel-1 of pixel 2k
        a[2 * i + 1] = t.w;           // channel-1 of pixel 2k+1
    }

    float mn = 1e30f, mx = -1e30f;
    unsigned cL = 0, cR = 0;
#pragma unroll
    for (int i = 0; i < 16; i++) {
        float v = a[i];
        mn = fminf(mn, v);
        mx = fmaxf(mx, v);
        unsigned pred = (unsigned)(v > EPS_LO);
        if (i < 8) cL += pred; else cR += pred;   // a idx <8 -> cols [0,256)
    }
    // rare borderline capture (expected ~0.1 per warp)
#pragma unroll
    for (int i = 0; i < 16; i++) {
        float v = a[i];
        if (v > EPS_LO && v <= EPS_HI) {
            unsigned half = (i < 8) ? 0u : 1u;
            unsigned idx = atomicAdd(&g_bl_n[b], 1u);
            if (idx < BLCAP) {
                g_bl_key[b][idx] = (half << 9) | (unsigned)row;
                g_bl_val[b][idx] = v;
            }
        }
    }

    cL = __reduce_add_sync(0xffffffffu, cL);
    cR = __reduce_add_sync(0xffffffffu, cR);
    if (lane == 0) {
        g_cnt[0][b][row] = (float)cL;
        g_cnt[1][b][row] = (float)cR;
    }

    // block-level min/max -> one atomic pair per block
#pragma unroll
    for (int o = 16; o; o >>= 1) {
        mn = fminf(mn, __shfl_xor_sync(0xffffffffu, mn, o));
        mx = fmaxf(mx, __shfl_xor_sync(0xffffffffu, mx, o));
    }
    __shared__ float smn[8], smx[8];
    int w = threadIdx.x >> 5;
    if (lane == 0) { smn[w] = mn; smx[w] = mx; }
    __syncthreads();
    if (threadIdx.x == 0) {
#pragma unroll
        for (int i = 1; i < 8; i++) { mn = fminf(mn, smn[i]); mx = fmaxf(mx, smx[i]); }
        atomicMin(&g_minb[b], __float_as_uint(mn));
        atomicMax(&g_maxb[b], __float_as_uint(mx));
    }
}

// ---------------- K3: correction + per (batch, contour) resampling ----------
// grid 128 (= batch*2), block 1024.
__global__ void k3_contour(const float4* __restrict__ in, float* __restrict__ out) {
    const float PI_F   = 3.14159265358979f;
    const float TWO_PI = 6.283185307179586f;
    const float TT0    = (float)(M_PI / 2.0);
    const float DT     = (float)(M_PI / 200.0);

    int unit = blockIdx.x;
    int b = unit >> 1, c = unit & 1;
    int tid = threadIdx.x;

    __shared__ float  s_x1[NH];
    __shared__ float2 s_rt[NH];    // (tt, r)
    __shared__ float  s_red[16];
    __shared__ float  s_bounds[2];

    float mn = __uint_as_float(g_minb[b]);
    float mx = __uint_as_float(g_maxb[b]);
    float h  = 0.5f * (mx - mn);    // exact predicate: (v - mn) > h
    unsigned nbl = g_bl_n[b];

    if (tid < NH) s_x1[tid] = g_cnt[c][b][tid];
    __syncthreads();

    // Window validity: all v <= EPS_LO must fail, all v > EPS_HI must pass.
    bool ok = ((EPS_LO - mn) <= h) && ((EPS_HI - mn) > h) && (nbl <= BLCAP);
    if (ok) {
        // exact correction of the tiny borderline set for this half
        for (unsigned i = tid; i < nbl; i += blockDim.x) {
            unsigned key = g_bl_key[b][i];
            if ((key >> 9) == (unsigned)c) {
                float v = g_bl_val[b][i];
                if (!((v - mn) > h)) atomicAdd(&s_x1[key & 511], -1.0f);
            }
        }
    } else {
        // never-expected exact fallback: full recount of this (b, c) half
        int w = tid >> 5, lane = tid & 31;
        for (int row = w; row < NH; row += 32) {
            const float4* p = in + ((size_t)(b * NH + row)) * 256 + c * 128;
            unsigned cnt = 0;
#pragma unroll
            for (int k = 0; k < 4; k++) {
                float4 v = p[lane + k * 32];
                cnt += (unsigned)((v.y - mn) > h) + (unsigned)((v.w - mn) > h);
            }
            cnt = __reduce_add_sync(0xffffffffu, cnt);
            if (lane == 0) s_x1[row] = (float)cnt;
        }
    }
    __syncthreads();

    // bounds: ythtop = 256 - sum(xa[0:256]), ythbottom = 256 + sum(xa[256:512])
    if (tid < NH) {
        float s = fminf(s_x1[tid], 1.0f);
#pragma unroll
        for (int o = 16; o; o >>= 1) s += __shfl_xor_sync(0xffffffffu, s, o);
        if ((tid & 31) == 0) s_red[tid >> 5] = s;
    }
    __syncthreads();
    if (tid == 0) {
        float st = 0.f, sb = 0.f;
#pragma unroll
        for (int i = 0; i < 8; i++)  st += s_red[i];
#pragma unroll
        for (int i = 8; i < 16; i++) sb += s_red[i];
        s_bounds[0] = 256.0f - st;
        s_bounds[1] = 256.0f + sb;
    }
    __syncthreads();

    if (tid < NH) {
        float x1 = s_x1[tid];
        float y1 = fminf(fmaxf((float)tid, s_bounds[0]), s_bounds[1]);
        float yc = y1 - 256.0f;
        float xc = -x1;
        float r  = sqrtf(xc * xc + yc * yc);
        float tt = atan2f(yc, xc);
        if (tt < 0.0f) tt += TWO_PI;   // fix_radians -> [0, 2pi)
        s_rt[tid] = make_float2(tt, r);
    }
    __syncthreads();

    // 4 threads per output point, 128 rows each. Only the nearest period
    // offset can have d^2 < 1 (offsets 2*pi apart); others clamp to
    // exp(-100) ~ 0 and are dropped.
    int n   = tid >> 2;              // 0..255 (real < 200)
    int sub = tid & 3;
    float ttn = TT0 + (float)n * DT;
    float num = 0.f, den = 0.f;
    int base = sub << 7;
#pragma unroll 8
    for (int m = 0; m < 128; m++) {
        float2 tr = s_rt[base + m];
        float d = tr.x - ttn;                 // in (-3pi/2, 3pi/2)
        d = (d >  PI_F) ? d - TWO_PI : d;
        d = (d < -PI_F) ? d + TWO_PI : d;
        float d2 = fminf(d * d, 1.0f);
        float wgt = __expf(-100.0f * d2);
        den += wgt;
        num = fmaf(wgt, tr.y, num);
    }
    num += __shfl_xor_sync(0xffffffffu, num, 1);
    den += __shfl_xor_sync(0xffffffffu, den, 1);
    num += __shfl_xor_sync(0xffffffffu, num, 2);
    den += __shfl_xor_sync(0xffffffffu, den, 2);

    if (sub == 0 && n < NPTS) {
        float rn = num / den;
        float x = fmaf(rn, cosf(ttn), 256.0f);
        float y = fmaf(rn, sinf(ttn), 256.0f);
        int idx; float xo;
        if (c == 0) { idx = n;        xo = x; }
        else        { idx = 399 - n;  xo = 512.0f - x; }
        out[((size_t)b * 400 + idx) * 2 + 0] = xo;
        out[((size_t)b * 400 + idx) * 2 + 1] = y;
    }
}

extern "C" void kernel_launch(void* const* d_in, const int* in_sizes, int n_in,
                              void* d_out, int out_size) {
    const float4* in = (const float4*)d_in[0];
    float* out = (float*)d_out;

    k0_init<<<1, 64>>>();
    kA_pass<<<4096, 256>>>(in);
    k3_contour<<<128, 1024>>>(in, out);
}

// round 4
// speedup vs baseline: 1.6292x; 1.0133x over previous
#include <cuda_runtime.h>
#include <math.h>

// Problem constants
#define NB    64
#define NH    512
#define NW    512
#define NPTS  200

#define EPS_LO 0.4999f
#define EPS_HI 0.5001f
#define ROWCAP 8          // borderline values stored per row (true count kept separately)
#define BPB    64         // kA blocks per batch

// ---------------- scratch (device globals; every slot written every call,
// so no init kernel and no resets are needed) ----------------
__device__ float  g_pmn[NB][BPB];
__device__ float  g_pmx[NB][BPB];
// g_cnt[half][batch][row]: half 0 = cols [0,256), half 1 = cols [256,512)
__device__ float  g_cnt[2][NB][NH];
__device__ int    g_blcnt[NB][NH];          // true borderline count per row
__device__ float  g_blv[NB][NH][ROWCAP];    // packed: +v -> half 0, -v -> half 1

// ---------------- KA: fused single pass (DRAM-bound, atomic-free) --------
// One warp per row, 8 warps/block, 64 blocks/batch, grid 4096.
__global__ void kA_pass(const float4* __restrict__ in) {
    int gwarp = (blockIdx.x * blockDim.x + threadIdx.x) >> 5;  // 0..32767
    int lane  = threadIdx.x & 31;
    int b   = gwarp >> 9;
    int row = gwarp & 511;

    const float4* p = in + ((size_t)(b * NH + row)) * 256;  // 256 float4/row

    // front-batched loads: 8 independent LDG.128 in flight
    float a[16];
#pragma unroll
    for (int i = 0; i < 8; i++) {
        float4 t = p[lane + i * 32];
        a[2 * i]     = t.y;            // channel-1 of pixel 2k
        a[2 * i + 1] = t.w;            // channel-1 of pixel 2k+1
    }

    float mn = 1e30f, mx = -1e30f;
    unsigned cL = 0, cR = 0;
#pragma unroll
    for (int i = 0; i < 16; i++) {
        float v = a[i];
        mn = fminf(mn, v);
        mx = fmaxf(mx, v);
        unsigned pred = (unsigned)(v > EPS_LO);
        if (i < 8) cL += pred; else cR += pred;   // idx <8 -> cols [0,256)
    }

    // warp-enumerated borderline capture into this row's fixed slots
    int base = 0;
#pragma unroll
    for (int i = 0; i < 16; i++) {
        float v = a[i];
        bool bl = (v > EPS_LO) && (v <= EPS_HI);
        unsigned mask = __ballot_sync(0xffffffffu, bl);
        if (bl) {
            int idx = base + __popc(mask & ((1u << lane) - 1u));
            if (idx < ROWCAP)
                g_blv[b][row][idx] = (i < 8) ? v : -v;   // sign encodes half
        }
        base += __popc(mask);
    }

    cL = __reduce_add_sync(0xffffffffu, cL);
    cR = __reduce_add_sync(0xffffffffu, cR);
    if (lane == 0) {
        g_cnt[0][b][row] = (float)cL;
        g_cnt[1][b][row] = (float)cR;
        g_blcnt[b][row]  = base;       // true count (may exceed ROWCAP -> fallback)
    }

    // block-level min/max partials (no atomics)
#pragma unroll
    for (int o = 16; o; o >>= 1) {
        mn = fminf(mn, __shfl_xor_sync(0xffffffffu, mn, o));
        mx = fmaxf(mx, __shfl_xor_sync(0xffffffffu, mx, o));
    }
    __shared__ float smn[8], smx[8];
    int w = threadIdx.x >> 5;
    if (lane == 0) { smn[w] = mn; smx[w] = mx; }
    __syncthreads();
    if (threadIdx.x == 0) {
#pragma unroll
        for (int i = 1; i < 8; i++) { mn = fminf(mn, smn[i]); mx = fmaxf(mx, smx[i]); }
        g_pmn[b][blockIdx.x & 63] = mn;
        g_pmx[b][blockIdx.x & 63] = mx;
    }
}

// ---------------- K3: minmax reduce + correction + resampling ----------
// grid 128 (= batch*2), block 1024.
__global__ void k3_contour(const float4* __restrict__ in, float* __restrict__ out) {
    const float PI_F   = 3.14159265358979f;
    const float TWO_PI = 6.283185307179586f;
    const float TT0    = (float)(M_PI / 2.0);
    const float DT     = (float)(M_PI / 200.0);

    int unit = blockIdx.x;
    int b = unit >> 1, c = unit & 1;
    int tid = threadIdx.x;

    __shared__ float  s_x1[NH];
    __shared__ float2 s_rt[NH];    // (tt, r)
    __shared__ float  s_red[16];
    __shared__ float  s_bounds[2];
    __shared__ float  s_mm[2];     // mn, mx
    __shared__ int    s_ovf;

    // reduce the 64 min/max partials (2 warps)
    if (tid == 0) s_ovf = 0;
    if (tid < BPB) {
        float v = g_pmn[b][tid];
#pragma unroll
        for (int o = 16; o; o >>= 1) v = fminf(v, __shfl_xor_sync(0xffffffffu, v, o));
        if ((tid & 31) == 0) s_red[tid >> 5] = v;
    } else if (tid < 2 * BPB) {
        float v = g_pmx[b][tid - BPB];
#pragma unroll
        for (int o = 16; o; o >>= 1) v = fmaxf(v, __shfl_xor_sync(0xffffffffu, v, o));
        if ((tid & 31) == 0) s_red[8 + ((tid - BPB) >> 5)] = v;
    }
    int blcnt = 0;
    if (tid < NH) {
        s_x1[tid] = g_cnt[c][b][tid];
        blcnt = g_blcnt[b][tid];
        if (blcnt > ROWCAP) s_ovf = 1;   // benign race: any writer sets 1
    }
    __syncthreads();
    if (tid == 0) {
        s_mm[0] = fminf(s_red[0], s_red[1]);
        s_mm[1] = fmaxf(s_red[8], s_red[9]);
    }
    __syncthreads();
    float mn = s_mm[0], mx = s_mm[1];
    float h  = 0.5f * (mx - mn);        // exact predicate: (v - mn) > h

    // Window validity: all v <= EPS_LO must fail, all v > EPS_HI must pass.
    bool ok = ((EPS_LO - mn) <= h) && ((EPS_HI - mn) > h) && (s_ovf == 0);
    if (ok) {
        // exact correction; each thread owns its row -> no atomics
        if (tid < NH) {
            float corr = 0.f;
            for (int j = 0; j < blcnt; j++) {
                float pv = g_blv[b][tid][j];
                int   half = pv < 0.0f;
                float v = fabsf(pv);
                if (half == c && !((v - mn) > h)) corr += 1.0f;
            }
            s_x1[tid] -= corr;
        }
    } else {
        // never-expected exact fallback: full recount of this (b, c) half
        int w = tid >> 5, lane = tid & 31;
        for (int row = w; row < NH; row += 32) {
            const float4* p = in + ((size_t)(b * NH + row)) * 256 + c * 128;
            unsigned cnt = 0;
#pragma unroll
            for (int k = 0; k < 4; k++) {
                float4 v = p[lane + k * 32];
                cnt += (unsigned)((v.y - mn) > h) + (unsigned)((v.w - mn) > h);
            }
            cnt = __reduce_add_sync(0xffffffffu, cnt);
            if (lane == 0) s_x1[row] = (float)cnt;
        }
    }
    __syncthreads();

    // bounds: ythtop = 256 - sum(xa[0:256]), ythbottom = 256 + sum(xa[256:512])
    if (tid < NH) {
        float s = fminf(s_x1[tid], 1.0f);
#pragma unroll
        for (int o = 16; o; o >>= 1) s += __shfl_xor_sync(0xffffffffu, s, o);
        if ((tid & 31) == 0) s_red[tid >> 5] = s;
    }
    __syncthreads();
    if (tid == 0) {
        float st = 0.f, sb = 0.f;
#pragma unroll
        for (int i = 0; i < 8; i++)  st += s_red[i];
#pragma unroll
        for (int i = 8; i < 16; i++) sb += s_red[i];
        s_bounds[0] = 256.0f - st;
        s_bounds[1] = 256.0f + sb;
    }
    __syncthreads();

    if (tid < NH) {
        float x1 = s_x1[tid];
        float y1 = fminf(fmaxf((float)tid, s_bounds[0]), s_bounds[1]);
        float yc = y1 - 256.0f;
        float xc = -x1;
        float r  = sqrtf(xc * xc + yc * yc);
        float tt = atan2f(yc, xc);
        if (tt < 0.0f) tt += TWO_PI;   // fix_radians -> [0, 2pi)
        s_rt[tid] = make_float2(tt, r);
    }
    __syncthreads();

    // 4 threads per output point, 128 rows each. Only the nearest period
    // offset can have d^2 < 1 (offsets 2*pi apart); the others clamp to
    // exp(-100) ~ 0 and are dropped.
    int n   = tid >> 2;              // 0..255 (real < 200)
    int sub = tid & 3;
    float ttn = TT0 + (float)n * DT;
    float num = 0.f, den = 0.f;
    int base = sub << 7;
#pragma unroll 8
    for (int m = 0; m < 128; m++) {
        float2 tr = s_rt[base + m];
        float d = tr.x - ttn;                 // in (-3pi/2, 3pi/2)
        d = (d >  PI_F) ? d - TWO_PI : d;
        d = (d < -PI_F) ? d + TWO_PI : d;
        float d2 = fminf(d * d, 1.0f);
        float wgt = __expf(-100.0f * d2);
        den += wgt;
        num = fmaf(wgt, tr.y, num);
    }
    num += __shfl_xor_sync(0xffffffffu, num, 1);
    den += __shfl_xor_sync(0xffffffffu, den, 1);
    num += __shfl_xor_sync(0xffffffffu, num, 2);
    den += __shfl_xor_sync(0xffffffffu, den, 2);

    if (sub == 0 && n < NPTS) {
        float rn = num / den;
        float x = fmaf(rn, cosf(ttn), 256.0f);
        float y = fmaf(rn, sinf(ttn), 256.0f);
        int idx; float xo;
        if (c == 0) { idx = n;        xo = x; }
        else        { idx = 399 - n;  xo = 512.0f - x; }
        out[((size_t)b * 400 + idx) * 2 + 0] = xo;
        out[((size_t)b * 400 + idx) * 2 + 1] = y;
    }
}

extern "C" void kernel_launch(void* const* d_in, const int* in_sizes, int n_in,
                              void* d_out, int out_size) {
    const float4* in = (const float4*)d_in[0];
    float* out = (float*)d_out;

    kA_pass<<<4096, 256>>>(in);
    k3_contour<<<128, 1024>>>(in, out);
}

// round 5
// speedup vs baseline: 1.9880x; 1.2202x over previous
#include <cuda_runtime.h>
#include <math.h>

// Problem constants
#define NB    64
#define NH    512
#define NW    512
#define NPTS  200

#define EPS_LO 0.4999f
#define EPS_HI 0.5001f
#define ROWCAP 8          // borderline values stored per row (true count kept separately)
#define BPB    64         // kA blocks per batch

// ---------------- scratch (device globals; every slot written every call,
// so no init kernel and no resets are needed) ----------------
__device__ float  g_pmn[NB][BPB];
__device__ float  g_pmx[NB][BPB];
// g_cnt[half][batch][row]: half 0 = cols [0,256), half 1 = cols [256,512)
__device__ float  g_cnt[2][NB][NH];
__device__ int    g_blcnt[NB][NH];          // true borderline count per row
__device__ float  g_blv[NB][NH][ROWCAP];    // packed: +v -> half 0, -v -> half 1

// ---------------- KA: fused single pass (DRAM-bound, atomic-free) --------
// One warp per row, 8 warps/block, 64 blocks/batch, grid 4096.
__global__ void kA_pass(const float4* __restrict__ in) {
    int gwarp = (blockIdx.x * blockDim.x + threadIdx.x) >> 5;  // 0..32767
    int lane  = threadIdx.x & 31;
    int b   = gwarp >> 9;
    int row = gwarp & 511;

    const float4* p = in + ((size_t)(b * NH + row)) * 256;  // 256 float4/row

    // front-batched loads: 8 independent LDG.128 in flight
    float a[16];
#pragma unroll
    for (int i = 0; i < 8; i++) {
        float4 t = p[lane + i * 32];
        a[2 * i]     = t.y;            // channel-1 of pixel 2k
        a[2 * i + 1] = t.w;            // channel-1 of pixel 2k+1
    }

    float mn = 1e30f, mx = -1e30f;
    unsigned cL = 0, cR = 0;
#pragma unroll
    for (int i = 0; i < 16; i++) {
        float v = a[i];
        mn = fminf(mn, v);
        mx = fmaxf(mx, v);
        unsigned pred = (unsigned)(v > EPS_LO);
        if (i < 8) cL += pred; else cR += pred;   // idx <8 -> cols [0,256)
    }

    // warp-enumerated borderline capture into this row's fixed slots
    int base = 0;
#pragma unroll
    for (int i = 0; i < 16; i++) {
        float v = a[i];
        bool bl = (v > EPS_LO) && (v <= EPS_HI);
        unsigned mask = __ballot_sync(0xffffffffu, bl);
        if (bl) {
            int idx = base + __popc(mask & ((1u << lane) - 1u));
            if (idx < ROWCAP)
                g_blv[b][row][idx] = (i < 8) ? v : -v;   // sign encodes half
        }
        base += __popc(mask);
    }

    cL = __reduce_add_sync(0xffffffffu, cL);
    cR = __reduce_add_sync(0xffffffffu, cR);
    if (lane == 0) {
        g_cnt[0][b][row] = (float)cL;
        g_cnt[1][b][row] = (float)cR;
        g_blcnt[b][row]  = base;       // true count (may exceed ROWCAP -> fallback)
    }

    // block-level min/max partials (no atomics)
#pragma unroll
    for (int o = 16; o; o >>= 1) {
        mn = fminf(mn, __shfl_xor_sync(0xffffffffu, mn, o));
        mx = fmaxf(mx, __shfl_xor_sync(0xffffffffu, mx, o));
    }
    __shared__ float smn[8], smx[8];
    int w = threadIdx.x >> 5;
    if (lane == 0) { smn[w] = mn; smx[w] = mx; }
    __syncthreads();
    if (threadIdx.x == 0) {
#pragma unroll
        for (int i = 1; i < 8; i++) { mn = fminf(mn, smn[i]); mx = fmaxf(mx, smx[i]); }
        g_pmn[b][blockIdx.x & 63] = mn;
        g_pmx[b][blockIdx.x & 63] = mx;
    }
}

// ---------------- K3: minmax reduce + correction + resampling ----------
// grid 128 (= batch*2), block 1024.
// Inner-loop SMEM reads are warp-uniform (sub = tid>>8) -> broadcast, N=1.
__global__ void k3_contour(const float4* __restrict__ in, float* __restrict__ out) {
    const float TWO_PI  = 6.283185307179586f;
    const float INV_2PI = 0.15915494309189535f;
    const float TT0     = (float)(M_PI / 2.0);
    const float DT      = (float)(M_PI / 200.0);
    const float NEXPK   = -144.26950408889634f;  // -100 * log2(e)

    int unit = blockIdx.x;
    int b = unit >> 1, c = unit & 1;
    int tid = threadIdx.x;

    __shared__ float  s_x1[NH];
    __shared__ float2 s_rt[NH];        // (tt, r)
    __shared__ float  s_red[16];
    __shared__ float  s_bounds[2];
    __shared__ float  s_mm[2];         // mn, mx
    __shared__ int    s_ovf;
    __shared__ float  s_num[4][256];
    __shared__ float  s_den[4][256];

    // reduce the 64 min/max partials (2 warps)
    if (tid == 0) s_ovf = 0;
    if (tid < BPB) {
        float v = g_pmn[b][tid];
#pragma unroll
        for (int o = 16; o; o >>= 1) v = fminf(v, __shfl_xor_sync(0xffffffffu, v, o));
        if ((tid & 31) == 0) s_red[tid >> 5] = v;
    } else if (tid < 2 * BPB) {
        float v = g_pmx[b][tid - BPB];
#pragma unroll
        for (int o = 16; o; o >>= 1) v = fmaxf(v, __shfl_xor_sync(0xffffffffu, v, o));
        if ((tid & 31) == 0) s_red[8 + ((tid - BPB) >> 5)] = v;
    }
    int blcnt = 0;
    if (tid < NH) {
        s_x1[tid] = g_cnt[c][b][tid];
        blcnt = g_blcnt[b][tid];
        if (blcnt > ROWCAP) s_ovf = 1;   // benign race: any writer sets 1
    }
    __syncthreads();
    if (tid == 0) {
        s_mm[0] = fminf(s_red[0], s_red[1]);
        s_mm[1] = fmaxf(s_red[8], s_red[9]);
    }
    __syncthreads();
    float mn = s_mm[0], mx = s_mm[1];
    float h  = 0.5f * (mx - mn);        // exact predicate: (v - mn) > h

    // Window validity: all v <= EPS_LO must fail, all v > EPS_HI must pass.
    bool ok = ((EPS_LO - mn) <= h) && ((EPS_HI - mn) > h) && (s_ovf == 0);
    if (ok) {
        // exact correction; each thread owns its row -> no atomics
        if (tid < NH) {
            float corr = 0.f;
            for (int j = 0; j < blcnt; j++) {
                float pv = g_blv[b][tid][j];
                int   half = pv < 0.0f;
                float v = fabsf(pv);
                if (half == c && !((v - mn) > h)) corr += 1.0f;
            }
            s_x1[tid] -= corr;
        }
    } else {
        // never-expected exact fallback: full recount of this (b, c) half
        int w = tid >> 5, lane = tid & 31;
        for (int row = w; row < NH; row += 32) {
            const float4* p = in + ((size_t)(b * NH + row)) * 256 + c * 128;
            unsigned cnt = 0;
#pragma unroll
            for (int k = 0; k < 4; k++) {
                float4 v = p[lane + k * 32];
                cnt += (unsigned)((v.y - mn) > h) + (unsigned)((v.w - mn) > h);
            }
            cnt = __reduce_add_sync(0xffffffffu, cnt);
            if (lane == 0) s_x1[row] = (float)cnt;
        }
    }
    __syncthreads();

    // bounds: ythtop = 256 - sum(xa[0:256]), ythbottom = 256 + sum(xa[256:512])
    if (tid < NH) {
        float s = fminf(s_x1[tid], 1.0f);
#pragma unroll
        for (int o = 16; o; o >>= 1) s += __shfl_xor_sync(0xffffffffu, s, o);
        if ((tid & 31) == 0) s_red[tid >> 5] = s;
    }
    __syncthreads();
    if (tid == 0) {
        float st = 0.f, sb = 0.f;
#pragma unroll
        for (int i = 0; i < 8; i++)  st += s_red[i];
#pragma unroll
        for (int i = 8; i < 16; i++) sb += s_red[i];
        s_bounds[0] = 256.0f - st;
        s_bounds[1] = 256.0f + sb;
    }
    __syncthreads();

    if (tid < NH) {
        float x1 = s_x1[tid];
        float y1 = fminf(fmaxf((float)tid, s_bounds[0]), s_bounds[1]);
        float yc = y1 - 256.0f;
        float xc = -x1;
        float r  = sqrtf(xc * xc + yc * yc);
        float tt = atan2f(yc, xc);
        if (tt < 0.0f) tt += TWO_PI;   // fix_radians -> [0, 2pi)
        s_rt[tid] = make_float2(tt, r);
    }
    __syncthreads();

    // 4 partial sums per output point. sub is warp-uniform so every SMEM
    // read in the hot loop is a broadcast (no bank conflicts).
    // Only the nearest period offset can have d^2 < 1 (offsets 2*pi apart);
    // the others clamp to exp(-100) ~ 0 and are dropped. Wrap via rint:
    // |d| < 3*pi/2 so rint(d/2pi) in {-1,0,1}.
    int n   = tid & 255;             // 0..255 (real < 200)
    int sub = tid >> 8;              // 0..3, warp-uniform
    float ttn = TT0 + (float)n * DT;
    float num = 0.f, den = 0.f;
    int base = sub << 7;
#pragma unroll 8
    for (int m = 0; m < 128; m++) {
        float2 tr = s_rt[base + m];
        float d = tr.x - ttn;                          // in (-3pi/2, 3pi/2)
        d = fmaf(-TWO_PI, rintf(d * INV_2PI), d);      // wrap to [-pi, pi]
        float d2 = fminf(d * d, 1.0f);
        float wgt = exp2f(d2 * NEXPK);                 // exp(-100*d2)
        den += wgt;
        num = fmaf(wgt, tr.y, num);
    }
    s_num[sub][n] = num;
    s_den[sub][n] = den;
    __syncthreads();

    if (tid < NPTS) {
        float nm = s_num[0][tid] + s_num[1][tid] + s_num[2][tid] + s_num[3][tid];
        float dn = s_den[0][tid] + s_den[1][tid] + s_den[2][tid] + s_den[3][tid];
        float ttn0 = TT0 + (float)tid * DT;
        float rn = nm / dn;
        float x = fmaf(rn, cosf(ttn0), 256.0f);
        float y = fmaf(rn, sinf(ttn0), 256.0f);
        int idx; float xo;
        if (c == 0) { idx = tid;       xo = x; }
        else        { idx = 399 - tid; xo = 512.0f - x; }
        out[((size_t)b * 400 + idx) * 2 + 0] = xo;
        out[((size_t)b * 400 + idx) * 2 + 1] = y;
    }
}

extern "C" void kernel_launch(void* const* d_in, const int* in_sizes, int n_in,
                              void* d_out, int out_size) {
    const float4* in = (const float4*)d_in[0];
    float* out = (float*)d_out;

    kA_pass<<<4096, 256>>>(in);
    k3_contour<<<128, 1024>>>(in, out);
}

// round 6
// speedup vs baseline: 2.1014x; 1.0571x over previous
#include <cuda_runtime.h>
#include <math.h>

// Problem constants
#define NB    64
#define NH    512
#define NW    512
#define NPTS  200

#define EPS_LO 0.4999f
#define EPS_HI 0.5001f
#define ROWCAP 8          // borderline values stored per row (true count kept separately)
#define BPB    64         // kA blocks per batch

// ---------------- scratch (device globals; every slot written every call,
// so no init kernel and no resets are needed) ----------------
__device__ float  g_pmn[NB][BPB];
__device__ float  g_pmx[NB][BPB];
// g_cnt[half][batch][row]: half 0 = cols [0,256), half 1 = cols [256,512)
__device__ float  g_cnt[2][NB][NH];
__device__ int    g_blcnt[NB][NH];          // true borderline count per row
__device__ float  g_blv[NB][NH][ROWCAP];    // packed: +v -> half 0, -v -> half 1

// ---------------- KA: fused single pass (DRAM-bound, atomic-free) --------
// One warp per row, 8 warps/block, 64 blocks/batch, grid 4096.
__global__ void kA_pass(const float4* __restrict__ in) {
    int gwarp = (blockIdx.x * blockDim.x + threadIdx.x) >> 5;  // 0..32767
    int lane  = threadIdx.x & 31;
    int b   = gwarp >> 9;
    int row = gwarp & 511;

    const float4* p = in + ((size_t)(b * NH + row)) * 256;  // 256 float4/row

    // front-batched loads: 8 independent LDG.128 in flight
    float a[16];
#pragma unroll
    for (int i = 0; i < 8; i++) {
        float4 t = p[lane + i * 32];
        a[2 * i]     = t.y;            // channel-1 of pixel 2k
        a[2 * i + 1] = t.w;            // channel-1 of pixel 2k+1
    }

    float mn = 1e30f, mx = -1e30f;
    unsigned cL = 0, cR = 0;
#pragma unroll
    for (int i = 0; i < 16; i++) {
        float v = a[i];
        mn = fminf(mn, v);
        mx = fmaxf(mx, v);
        unsigned pred = (unsigned)(v > EPS_LO);
        if (i < 8) cL += pred; else cR += pred;   // idx <8 -> cols [0,256)
    }

    // warp-enumerated borderline capture into this row's fixed slots
    int base = 0;
#pragma unroll
    for (int i = 0; i < 16; i++) {
        float v = a[i];
        bool bl = (v > EPS_LO) && (v <= EPS_HI);
        unsigned mask = __ballot_sync(0xffffffffu, bl);
        if (bl) {
            int idx = base + __popc(mask & ((1u << lane) - 1u));
            if (idx < ROWCAP)
                g_blv[b][row][idx] = (i < 8) ? v : -v;   // sign encodes half
        }
        base += __popc(mask);
    }

    cL = __reduce_add_sync(0xffffffffu, cL);
    cR = __reduce_add_sync(0xffffffffu, cR);
    if (lane == 0) {
        g_cnt[0][b][row] = (float)cL;
        g_cnt[1][b][row] = (float)cR;
        g_blcnt[b][row]  = base;       // true count (may exceed ROWCAP -> fallback)
    }

    // block-level min/max partials (no atomics)
#pragma unroll
    for (int o = 16; o; o >>= 1) {
        mn = fminf(mn, __shfl_xor_sync(0xffffffffu, mn, o));
        mx = fmaxf(mx, __shfl_xor_sync(0xffffffffu, mx, o));
    }
    __shared__ float smn[8], smx[8];
    int w = threadIdx.x >> 5;
    if (lane == 0) { smn[w] = mn; smx[w] = mx; }
    __syncthreads();
    if (threadIdx.x == 0) {
#pragma unroll
        for (int i = 1; i < 8; i++) { mn = fminf(mn, smn[i]); mx = fmaxf(mx, smx[i]); }
        g_pmn[b][blockIdx.x & 63] = mn;
        g_pmx[b][blockIdx.x & 63] = mx;
    }
}

// ---------------- K3: minmax reduce + correction + resampling ----------
// grid 128 (= batch*2), block 1024.
// Hot loop: warp-uniform float4 SMEM broadcasts; no wrap (see range proof);
// clamp folded into the exponent: exp2(min(d^2,1)*K) = exp2(max(d^2*K, K)).
__global__ void k3_contour(const float4* __restrict__ in, float* __restrict__ out) {
    const float TWO_PI = 6.283185307179586f;
    const float TT0    = (float)(M_PI / 2.0);
    const float DT     = (float)(M_PI / 200.0);
    const float NEXPK  = -144.26950408889634f;  // -100 * log2(e)

    int unit = blockIdx.x;
    int b = unit >> 1, c = unit & 1;
    int tid = threadIdx.x;

    __shared__ float  s_x1[NH];
    __shared__ float2 s_rt[NH];        // (tt, r); read as float4 in hot loop
    __shared__ float  s_red[16];
    __shared__ float  s_bounds[2];
    __shared__ float  s_mm[2];         // mn, mx
    __shared__ int    s_ovf;
    __shared__ float  s_num[4][256];
    __shared__ float  s_den[4][256];

    // reduce the 64 min/max partials (2 warps)
    if (tid == 0) s_ovf = 0;
    if (tid < BPB) {
        float v = g_pmn[b][tid];
#pragma unroll
        for (int o = 16; o; o >>= 1) v = fminf(v, __shfl_xor_sync(0xffffffffu, v, o));
        if ((tid & 31) == 0) s_red[tid >> 5] = v;
    } else if (tid < 2 * BPB) {
        float v = g_pmx[b][tid - BPB];
#pragma unroll
        for (int o = 16; o; o >>= 1) v = fmaxf(v, __shfl_xor_sync(0xffffffffu, v, o));
        if ((tid & 31) == 0) s_red[8 + ((tid - BPB) >> 5)] = v;
    }
    int blcnt = 0;
    if (tid < NH) {
        s_x1[tid] = g_cnt[c][b][tid];
        blcnt = g_blcnt[b][tid];
        if (blcnt > ROWCAP) s_ovf = 1;   // benign race: any writer sets 1
    }
    __syncthreads();
    if (tid == 0) {
        s_mm[0] = fminf(s_red[0], s_red[1]);
        s_mm[1] = fmaxf(s_red[8], s_red[9]);
    }
    __syncthreads();
    float mn = s_mm[0], mx = s_mm[1];
    float h  = 0.5f * (mx - mn);        // exact predicate: (v - mn) > h

    // Window validity: all v <= EPS_LO must fail, all v > EPS_HI must pass.
    bool ok = ((EPS_LO - mn) <= h) && ((EPS_HI - mn) > h) && (s_ovf == 0);
    if (ok) {
        // exact correction; each thread owns its row -> no atomics
        if (tid < NH) {
            float corr = 0.f;
            for (int j = 0; j < blcnt; j++) {
                float pv = g_blv[b][tid][j];
                int   half = pv < 0.0f;
                float v = fabsf(pv);
                if (half == c && !((v - mn) > h)) corr += 1.0f;
            }
            s_x1[tid] -= corr;
        }
    } else {
        // never-expected exact fallback: full recount of this (b, c) half
        int w = tid >> 5, lane = tid & 31;
        for (int row = w; row < NH; row += 32) {
            const float4* p = in + ((size_t)(b * NH + row)) * 256 + c * 128;
            unsigned cnt = 0;
#pragma unroll
            for (int k = 0; k < 4; k++) {
                float4 v = p[lane + k * 32];
                cnt += (unsigned)((v.y - mn) > h) + (unsigned)((v.w - mn) > h);
            }
            cnt = __reduce_add_sync(0xffffffffu, cnt);
            if (lane == 0) s_x1[row] = (float)cnt;
        }
    }
    __syncthreads();

    // bounds: ythtop = 256 - sum(xa[0:256]), ythbottom = 256 + sum(xa[256:512])
    if (tid < NH) {
        float s = fminf(s_x1[tid], 1.0f);
#pragma unroll
        for (int o = 16; o; o >>= 1) s += __shfl_xor_sync(0xffffffffu, s, o);
        if ((tid & 31) == 0) s_red[tid >> 5] = s;
    }
    __syncthreads();
    if (tid == 0) {
        float st = 0.f, sb = 0.f;
#pragma unroll
        for (int i = 0; i < 8; i++)  st += s_red[i];
#pragma unroll
        for (int i = 8; i < 16; i++) sb += s_red[i];
        s_bounds[0] = 256.0f - st;
        s_bounds[1] = 256.0f + sb;
    }
    __syncthreads();

    if (tid < NH) {
        float x1 = s_x1[tid];
        float y1 = fminf(fmaxf((float)tid, s_bounds[0]), s_bounds[1]);
        float yc = y1 - 256.0f;
        float xc = -x1;
        float r  = sqrtf(xc * xc + yc * yc);
        float tt = atan2f(yc, xc);
        if (tt < 0.0f) tt += TWO_PI;   // fix_radians -> [0, 2pi)
        s_rt[tid] = make_float2(tt, r);
    }
    __syncthreads();

    // 4 partial sums per output point; sub = tid>>8 is warp-uniform so the
    // SMEM reads are broadcasts. Range proof: xc <= 0 always, so
    // tt = atan2(yc, xc) in [pi/2, 3pi/2]; ttn in [pi/2, 3pi/2)  =>
    // d = tt - ttn in (-pi, pi] -- no wrap needed, and the +-2pi period
    // candidates always clamp to d^2=1 -> exp(-100) ~ 0 (dropped).
    int n   = tid & 255;             // 0..255 (real < 200)
    int sub = tid >> 8;              // 0..3, warp-uniform
    float ttn = TT0 + (float)n * DT;
    float num = 0.f, den = 0.f;
    const float4* rt4 = (const float4*)s_rt;   // (tt0, r0, tt1, r1)
    int base4 = sub << 6;                      // 64 float4 per sub-range
#pragma unroll 8
    for (int m = 0; m < 64; m++) {
        float4 q = rt4[base4 + m];
        float d0 = q.x - ttn;
        float w0 = exp2f(fmaxf(d0 * d0 * NEXPK, NEXPK));
        den += w0;
        num = fmaf(w0, q.y, num);
        float d1 = q.z - ttn;
        float w1 = exp2f(fmaxf(d1 * d1 * NEXPK, NEXPK));
        den += w1;
        num = fmaf(w1, q.w, num);
    }
    s_num[sub][n] = num;
    s_den[sub][n] = den;
    __syncthreads();

    if (tid < NPTS) {
        float nm = s_num[0][tid] + s_num[1][tid] + s_num[2][tid] + s_num[3][tid];
        float dn = s_den[0][tid] + s_den[1][tid] + s_den[2][tid] + s_den[3][tid];
        float ttn0 = TT0 + (float)tid * DT;
        float rn = nm / dn;
        float x = fmaf(rn, cosf(ttn0), 256.0f);
        float y = fmaf(rn, sinf(ttn0), 256.0f);
        int idx; float xo;
        if (c == 0) { idx = tid;       xo = x; }
        else        { idx = 399 - tid; xo = 512.0f - x; }
        out[((size_t)b * 400 + idx) * 2 + 0] = xo;
        out[((size_t)b * 400 + idx) * 2 + 1] = y;
    }
}

extern "C" void kernel_launch(void* const* d_in, const int* in_sizes, int n_in,
                              void* d_out, int out_size) {
    const float4* in = (const float4*)d_in[0];
    float* out = (float*)d_out;

    kA_pass<<<4096, 256>>>(in);
    k3_contour<<<128, 1024>>>(in, out);
}